// round 14
// baseline (speedup 1.0000x reference)
#include <cuda_runtime.h>
#include <cuda_bf16.h>
#include <cstdint>

#define Bm   32
#define Dm   2560
#define Em   5120
#define RK   160
#define STn  16
#define BE   (Bm*Em)
#define BD   (Bm*Dm)
#define KS_IN   8
#define KS_OUT  32
#define KS_DBC  40

typedef unsigned long long ull;

// -------- scratch ----------
__device__ float g_p_ssm[KS_IN * BE];
__device__ float g_p_mlp[KS_IN * BE];
__device__ float g_xt   [BE];
__device__ float g_res  [BE];
__device__ float g_dbcp [KS_DBC * Bm * 192];
__device__ float g_z    [BE];
__device__ float g_A    [Em * STn];   // -exp(A_log), precomputed once

// -------- helpers ----------
__device__ __forceinline__ ull pack2(float x, float y) {
    ull r;
    asm("mov.b64 %0, {%1,%2};" : "=l"(r) : "f"(x), "f"(y));
    return r;
}
__device__ __forceinline__ void fma2(ull& d, ull a, ull b) {
    asm("fma.rn.f32x2 %0, %1, %2, %0;" : "+l"(d) : "l"(a), "l"(b));
}
__device__ __forceinline__ float2 unpack2(ull v) {
    float2 r;
    asm("mov.b64 {%0,%1}, %2;" : "=f"(r.x), "=f"(r.y) : "l"(v));
    return r;
}
__device__ __forceinline__ float silu_f(float v) {
    return v * (1.0f / (1.0f + __expf(-v)));
}
__device__ __forceinline__ uint32_t smem_u32(const void* p) {
    uint32_t a;
    asm("{ .reg .u64 t; cvta.to.shared.u64 t, %1; cvt.u32.u64 %0, t; }"
        : "=r"(a) : "l"(p));
    return a;
}
__device__ __forceinline__ void cp_async16(uint32_t dst, const void* src) {
    asm volatile("cp.async.cg.shared.global [%0], [%1], 16;"
                 :: "r"(dst), "l"(src));
}
#define CP_COMMIT()  asm volatile("cp.async.commit_group;")
#define CP_WAIT(n)   asm volatile("cp.async.wait_group %0;" :: "n"(n))

__device__ __forceinline__ uint32_t f2tf(float v) {
    uint32_t u;
    asm("cvt.rna.tf32.f32 %0, %1;" : "=r"(u) : "f"(v));
    return u;
}
__device__ __forceinline__ void mma_tf32(float* d, const uint32_t* a,
                                         uint32_t b0, uint32_t b1) {
    asm volatile(
        "mma.sync.aligned.m16n8k8.row.col.f32.tf32.tf32.f32 "
        "{%0,%1,%2,%3}, {%4,%5,%6,%7}, {%8,%9}, {%0,%1,%2,%3};"
        : "+f"(d[0]), "+f"(d[1]), "+f"(d[2]), "+f"(d[3])
        : "r"(a[0]), "r"(a[1]), "r"(a[2]), "r"(a[3]), "r"(b0), "r"(b1));
}

// ---------------------------------------------------------------------------
// tf32 tensor-core 32-row GEMM: N-tile 128, 128 threads (4 warps).
// W: 3-stage cp.async pipeline, ONE __syncthreads per chunk.
// X: per-chunk tf32 double buffer, LDG prefetched one chunk ahead.
// EPI = 0: write partials to part[ksIdx]. EPI = 1: atomicAdd into part.
// ---------------------------------------------------------------------------
template <int KPER, int NCOLS, int XSTRIDE, int EPI>
__device__ __forceinline__
void gemm32_tf2(const float* __restrict__ Xp, const float* __restrict__ W,
                float* __restrict__ part, int n0, int kbase, int ksIdx) {
    __shared__ __align__(16) float    Wfs[3][16][136];
    __shared__ __align__(16) uint32_t Xs[2][32][20];

    const int t    = threadIdx.x;
    const int lane = t & 31;
    const int warp = t >> 5;
    const int g = lane >> 2;
    const int q = lane & 3;
    constexpr int NCH = KPER / 16;

    float d[2][4][4];
#pragma unroll
    for (int m = 0; m < 2; m++)
#pragma unroll
        for (int s = 0; s < 4; s++)
#pragma unroll
            for (int u = 0; u < 4; u++) d[m][s][u] = 0.0f;

    auto issue_w = [&](int c) {
        const int kg = kbase + c * 16;
        const int buf = c % 3;
#pragma unroll
        for (int r = 0; r < 4; r++) {
            int s = t + r * 128, k = s >> 5, seg = s & 31;
            cp_async16(smem_u32(&Wfs[buf][k][seg * 4]),
                       &W[(size_t)(kg + k) * NCOLS + n0 + seg * 4]);
        }
        CP_COMMIT();
    };
    float xreg[4];
    auto load_x = [&](int c) {
        const int kg = kbase + c * 16;
#pragma unroll
        for (int r = 0; r < 4; r++) {
            int i = t + r * 128, b = i >> 4, k = i & 15;
            xreg[r] = Xp[(size_t)b * XSTRIDE + kg + k];
        }
    };
    auto store_x = [&](int c) {
        uint32_t* dst = &Xs[c & 1][0][0];
#pragma unroll
        for (int r = 0; r < 4; r++) {
            int i = t + r * 128, b = i >> 4, k = i & 15;
            dst[b * 20 + k] = f2tf(xreg[r]);
        }
    };

    issue_w(0);
    if (NCH > 1) issue_w(1);
    load_x(0);
    store_x(0);
    if (NCH > 1) load_x(1);

    for (int c = 0; c < NCH; c++) {
        if (c + 1 < NCH) { CP_WAIT(1); } else { CP_WAIT(0); }
        __syncthreads();
        if (c + 2 < NCH) issue_w(c + 2);
        if (c + 1 < NCH) store_x(c + 1);
        if (c + 2 < NCH) load_x(c + 2);

        const int buf = c % 3;
        const uint32_t* Xc = &Xs[c & 1][0][0];
#pragma unroll
        for (int s = 0; s < 2; s++) {
            const int kA = s * 8;
            uint32_t a0[4], a1[4];
            a0[0] = Xc[g * 20 + kA + q];
            a0[1] = Xc[(g + 8) * 20 + kA + q];
            a0[2] = Xc[g * 20 + kA + q + 4];
            a0[3] = Xc[(g + 8) * 20 + kA + q + 4];
            a1[0] = Xc[(16 + g) * 20 + kA + q];
            a1[1] = Xc[(24 + g) * 20 + kA + q];
            a1[2] = Xc[(16 + g) * 20 + kA + q + 4];
            a1[3] = Xc[(24 + g) * 20 + kA + q + 4];
#pragma unroll
            for (int nt = 0; nt < 4; nt++) {
                const int col = warp * 32 + nt * 8 + g;
                uint32_t b0 = f2tf(Wfs[buf][s * 8 + q][col]);
                uint32_t b1 = f2tf(Wfs[buf][s * 8 + q + 4][col]);
                mma_tf32(d[0][nt], a0, b0, b1);
                mma_tf32(d[1][nt], a1, b0, b1);
            }
        }
    }
#pragma unroll
    for (int mt = 0; mt < 2; mt++) {
#pragma unroll
        for (int s = 0; s < 4; s++) {
            int col = n0 + warp * 32 + s * 8 + q * 2;
            if (EPI == 0) {
                size_t r0 = (size_t)(ksIdx * Bm + mt * 16 + g) * NCOLS + col;
                size_t r1 = (size_t)(ksIdx * Bm + mt * 16 + g + 8) * NCOLS + col;
                *reinterpret_cast<float2*>(&part[r0]) =
                    make_float2(d[mt][s][0], d[mt][s][1]);
                *reinterpret_cast<float2*>(&part[r1]) =
                    make_float2(d[mt][s][2], d[mt][s][3]);
            } else {
                size_t r0 = (size_t)(mt * 16 + g) * NCOLS + col;
                size_t r1 = (size_t)(mt * 16 + g + 8) * NCOLS + col;
                atomicAdd(&part[r0],     d[mt][s][0]);
                atomicAdd(&part[r0 + 1], d[mt][s][1]);
                atomicAdd(&part[r1],     d[mt][s][2]);
                atomicAdd(&part[r1 + 1], d[mt][s][3]);
            }
        }
    }
}

// Fused input GEMMs: blockIdx.z selects ssm / mlp. grid(40, KS_IN, 2).
__global__ __launch_bounds__(128)
void gemm_in_kernel(const float* __restrict__ X,
                    const float* __restrict__ W0,
                    const float* __restrict__ W1) {
    const float* W = (blockIdx.z == 0) ? W0 : W1;
    float* part    = (blockIdx.z == 0) ? g_p_ssm : g_p_mlp;
    constexpr int KPER = Dm / KS_IN;  // 320
    gemm32_tf2<KPER, Em, Dm, 0>(X, W, part, blockIdx.x * 128,
                                blockIdx.y * KPER, blockIdx.y);
}
// Output GEMM: atomicAdd directly into d_out (zeroed by ssm_kernel).
__global__ __launch_bounds__(128)
void gemm_out_kernel(const float* __restrict__ W, float* __restrict__ out) {
    constexpr int KPER = Em / KS_OUT;  // 160
    gemm32_tf2<KPER, Dm, Em, 1>(g_z, W, out, blockIdx.x * 128,
                                blockIdx.y * KPER, blockIdx.y);
}

// ---------------------------------------------------------------------------
// dbc GEMM: xt(32,5120) @ Wx(5120,192), f32x2 pipelined. grid(3, KS_DBC).
// ---------------------------------------------------------------------------
__global__ __launch_bounds__(128)
void dbc_gemm_kernel(const float* __restrict__ Wx) {
    __shared__ ull Wsb[2][32][32];
    __shared__ ull Xsb[2][32][33];

    const int t  = threadIdx.x;
    const int n0 = blockIdx.x * 64;
    constexpr int KPER = Em / KS_DBC;  // 128
    constexpr int NCH  = KPER / 32;    // 4
    const int kbase = blockIdx.y * KPER;
    const int cg = t & 15;
    const int rg = t >> 4;
    const int b0 = rg * 4;
    const int qu = cg * 2;

    ull acc[4][2];
#pragma unroll
    for (int j = 0; j < 4; j++) { acc[j][0] = 0ULL; acc[j][1] = 0ULL; }

    float xreg[8];
    {
        const int kg = kbase;
#pragma unroll
        for (int r = 0; r < 4; r++) {
            int s = t + r * 128, row = s >> 4, c16 = s & 15;
            cp_async16(smem_u32(&Wsb[0][row][c16 * 2]),
                       &Wx[(size_t)(kg + row) * 192 + n0 + c16 * 4]);
        }
        CP_COMMIT();
#pragma unroll
        for (int r = 0; r < 8; r++) {
            int i = t + r * 128, b = i >> 5, kk = i & 31;
            xreg[r] = g_xt[b * Em + kg + kk];
        }
    }

    for (int c = 0; c < NCH; c++) {
        const int p = c & 1;
#pragma unroll
        for (int r = 0; r < 8; r++) {
            int i = t + r * 128, b = i >> 5, kk = i & 31;
            Xsb[p][kk][b] = pack2(xreg[r], xreg[r]);
        }
        if (c + 1 < NCH) {
            const int kg = kbase + (c + 1) * 32;
#pragma unroll
            for (int r = 0; r < 4; r++) {
                int s = t + r * 128, row = s >> 4, c16 = s & 15;
                cp_async16(smem_u32(&Wsb[1 - p][row][c16 * 2]),
                           &Wx[(size_t)(kg + row) * 192 + n0 + c16 * 4]);
            }
            CP_COMMIT();
#pragma unroll
            for (int r = 0; r < 8; r++) {
                int i = t + r * 128, b = i >> 5, kk = i & 31;
                xreg[r] = g_xt[b * Em + kg + kk];
            }
            CP_WAIT(1);
        } else {
            CP_WAIT(0);
        }
        __syncthreads();
#pragma unroll
        for (int kk = 0; kk < 32; kk++) {
            ulonglong2 w = *reinterpret_cast<const ulonglong2*>(&Wsb[p][kk][qu]);
            ull xs[4] = {Xsb[p][kk][b0], Xsb[p][kk][b0 + 1],
                         Xsb[p][kk][b0 + 2], Xsb[p][kk][b0 + 3]};
#pragma unroll
            for (int j = 0; j < 4; j++) {
                fma2(acc[j][0], xs[j], w.x);
                fma2(acc[j][1], xs[j], w.y);
            }
        }
        __syncthreads();
    }
#pragma unroll
    for (int j = 0; j < 4; j++) {
        float2 a0 = unpack2(acc[j][0]);
        float2 a1 = unpack2(acc[j][1]);
        *reinterpret_cast<float4*>(
            &g_dbcp[((size_t)blockIdx.y * Bm + b0 + j) * 192 + n0 + cg * 4]) =
            make_float4(a0.x, a0.y, a1.x, a1.y);
    }
}

// ---------------------------------------------------------------------------
// conv + SiLU + precompute g_A = -exp(A_log).
// ---------------------------------------------------------------------------
__global__ __launch_bounds__(256)
void conv_silu_kernel(const float* __restrict__ conv_w,
                      const float* __restrict__ conv_b,
                      const float* __restrict__ conv_states,
                      const float* __restrict__ A_log) {
    int idx = blockIdx.x * 256 + threadIdx.x;
    float xssm = 0.0f, xmlp = 0.0f;
#pragma unroll
    for (int ks = 0; ks < KS_IN; ks++) {
        xssm += g_p_ssm[idx + ks * BE];
        xmlp += g_p_mlp[idx + ks * BE];
    }
    float c = conv_b[idx];
    c += conv_states[idx]          * conv_w[idx];
    c += conv_states[idx + BE]     * conv_w[idx + BE];
    c += conv_states[idx + 2 * BE] * conv_w[idx + 2 * BE];
    c += xssm                      * conv_w[idx + 3 * BE];
    g_xt[idx]  = silu_f(c);
    g_res[idx] = silu_f(xmlp);
    if (idx < Em * STn)
        g_A[idx] = -__expf(A_log[idx]);
}

// ---------------------------------------------------------------------------
// ssm: block-local dbc reduce (2 rows -> smem) + dt GEMM + SSM + z = y*res.
// Also zeroes d_out for gemm_out's atomic accumulation (exactly BD threads).
// ---------------------------------------------------------------------------
__global__ __launch_bounds__(256)
void ssm_kernel(const float* __restrict__ W_dt,
                const float* __restrict__ dt_bias,
                const float* __restrict__ Dv,
                const float* __restrict__ h,
                float* __restrict__ out) {
    __shared__ float s_dbc[384];
    const int t   = threadIdx.x;
    const int gid = blockIdx.x * 256 + t;   // [0, 16*Em)
    const int e   = gid % Em;
    const int b0  = (gid / Em) * 2;

    out[gid] = 0.0f;   // zero d_out slice for gemm_out atomics

    // reduce this block's two dbc rows from partials (L2-hot) into smem
    for (int idx = t; idx < 384; idx += 256) {
        int row = idx / 192;
        int col = idx - row * 192;
        int o = (b0 + row) * 192 + col;
        float s = 0.0f;
#pragma unroll
        for (int ks = 0; ks < KS_DBC; ks++) s += g_dbcp[ks * (Bm * 192) + o];
        s_dbc[idx] = s;
    }
    __syncthreads();

    float dt0 = 0.0f, dt1 = 0.0f;
#pragma unroll 8
    for (int k = 0; k < RK; k++) {
        float wd = W_dt[(size_t)k * Em + e];
        dt0 += s_dbc[k] * wd;
        dt1 += s_dbc[192 + k] * wd;
    }

    float bias = dt_bias[e];
    float dval = Dv[e];
    float An[STn];
#pragma unroll
    for (int n = 0; n < STn; n += 4) {
        float4 a = *reinterpret_cast<const float4*>(&g_A[(size_t)e * STn + n]);
        An[n] = a.x; An[n + 1] = a.y; An[n + 2] = a.z; An[n + 3] = a.w;
    }

    float dts[2] = {dt0, dt1};
#pragma unroll
    for (int j = 0; j < 2; j++) {
        int b = b0 + j;
        float s = dts[j] + bias;
        float dt = (s > 20.0f) ? s : __logf(1.0f + __expf(s));
        float xt = g_xt[b * Em + e];
        const float* hb = &h[((size_t)b * Em + e) * STn];
        float y = 0.0f;
#pragma unroll
        for (int n = 0; n < STn; n++) {
            float Bv = s_dbc[j * 192 + 160 + n];
            float Cv = s_dbc[j * 192 + 176 + n];
            float dA = __expf(dt * An[n]);
            float hn = hb[n] * dA + dt * Bv * xt;
            y += hn * Cv;
        }
        y += dval * xt;
        g_z[b * Em + e] = y * g_res[b * Em + e];
    }
}

// ---------------------------------------------------------------------------
extern "C" void kernel_launch(void* const* d_in, const int* in_sizes, int n_in,
                              void* d_out, int out_size) {
    const float* x        = (const float*)d_in[0];
    const float* W_in_ssm = (const float*)d_in[1];
    const float* W_in_mlp = (const float*)d_in[2];
    const float* W_out    = (const float*)d_in[3];
    const float* conv_w   = (const float*)d_in[4];
    const float* conv_b   = (const float*)d_in[5];
    const float* conv_st  = (const float*)d_in[6];
    const float* Wx       = (const float*)d_in[7];
    const float* W_dt     = (const float*)d_in[8];
    const float* dt_bias  = (const float*)d_in[9];
    const float* A_log    = (const float*)d_in[10];
    const float* Dvec     = (const float*)d_in[11];
    const float* h        = (const float*)d_in[12];
    float* out = (float*)d_out;

    gemm_in_kernel<<<dim3(40, KS_IN, 2), 128>>>(x, W_in_ssm, W_in_mlp);
    conv_silu_kernel<<<BE / 256, 256>>>(conv_w, conv_b, conv_st, A_log);
    dbc_gemm_kernel<<<dim3(3, KS_DBC), 128>>>(Wx);
    ssm_kernel<<<320, 256>>>(W_dt, dt_bias, Dvec, h, out);
    gemm_out_kernel<<<dim3(20, KS_OUT), 128>>>(W_out, out);
}

// round 15
// speedup vs baseline: 1.0966x; 1.0966x over previous
#include <cuda_runtime.h>
#include <cuda_bf16.h>
#include <cstdint>

#define Bm   32
#define Dm   2560
#define Em   5120
#define RK   160
#define STn  16
#define BE   (Bm*Em)
#define BD   (Bm*Dm)
#define KS_IN   8
#define KS_OUT  32
#define KS_DBC  40

typedef unsigned long long ull;

// -------- scratch ----------
__device__ float g_p_ssm[KS_IN * BE];
__device__ float g_p_mlp[KS_IN * BE];
__device__ float g_xt   [BE];
__device__ float g_res  [BE];
__device__ float g_dbcp [KS_DBC * Bm * 192];
__device__ float g_z    [BE];
__device__ float g_A    [Em * STn];   // -exp(A_log), precomputed once

// -------- helpers ----------
__device__ __forceinline__ ull pack2(float x, float y) {
    ull r;
    asm("mov.b64 %0, {%1,%2};" : "=l"(r) : "f"(x), "f"(y));
    return r;
}
__device__ __forceinline__ void fma2(ull& d, ull a, ull b) {
    asm("fma.rn.f32x2 %0, %1, %2, %0;" : "+l"(d) : "l"(a), "l"(b));
}
__device__ __forceinline__ float2 unpack2(ull v) {
    float2 r;
    asm("mov.b64 {%0,%1}, %2;" : "=f"(r.x), "=f"(r.y) : "l"(v));
    return r;
}
__device__ __forceinline__ float silu_f(float v) {
    return v * (1.0f / (1.0f + __expf(-v)));
}
__device__ __forceinline__ uint32_t smem_u32(const void* p) {
    uint32_t a;
    asm("{ .reg .u64 t; cvta.to.shared.u64 t, %1; cvt.u32.u64 %0, t; }"
        : "=r"(a) : "l"(p));
    return a;
}
__device__ __forceinline__ void cp_async16(uint32_t dst, const void* src) {
    asm volatile("cp.async.cg.shared.global [%0], [%1], 16;"
                 :: "r"(dst), "l"(src));
}
#define CP_COMMIT()  asm volatile("cp.async.commit_group;")
#define CP_WAIT(n)   asm volatile("cp.async.wait_group %0;" :: "n"(n))

__device__ __forceinline__ uint32_t f2tf(float v) {
    uint32_t u;
    asm("cvt.rna.tf32.f32 %0, %1;" : "=r"(u) : "f"(v));
    return u;
}
__device__ __forceinline__ void mma_tf32(float* d, const uint32_t* a,
                                         uint32_t b0, uint32_t b1) {
    asm volatile(
        "mma.sync.aligned.m16n8k8.row.col.f32.tf32.tf32.f32 "
        "{%0,%1,%2,%3}, {%4,%5,%6,%7}, {%8,%9}, {%0,%1,%2,%3};"
        : "+f"(d[0]), "+f"(d[1]), "+f"(d[2]), "+f"(d[3])
        : "r"(a[0]), "r"(a[1]), "r"(a[2]), "r"(a[3]), "r"(b0), "r"(b1));
}

// ---------------------------------------------------------------------------
// tf32 tensor-core 32-row GEMM: N-tile 128, 128 threads (4 warps).
// W: 3-stage cp.async pipeline, ONE __syncthreads per chunk.
// X: per-chunk tf32 double buffer, LDG prefetched one chunk ahead.
// EPI = 0: write partials to part[ksIdx]. EPI = 1: atomicAdd into part.
// ---------------------------------------------------------------------------
template <int KPER, int NCOLS, int XSTRIDE, int EPI>
__device__ __forceinline__
void gemm32_tf2(const float* __restrict__ Xp, const float* __restrict__ W,
                float* __restrict__ part, int n0, int kbase, int ksIdx) {
    __shared__ __align__(16) float    Wfs[3][16][136];
    __shared__ __align__(16) uint32_t Xs[2][32][20];

    const int t    = threadIdx.x;
    const int lane = t & 31;
    const int warp = t >> 5;
    const int g = lane >> 2;
    const int q = lane & 3;
    constexpr int NCH = KPER / 16;

    float d[2][4][4];
#pragma unroll
    for (int m = 0; m < 2; m++)
#pragma unroll
        for (int s = 0; s < 4; s++)
#pragma unroll
            for (int u = 0; u < 4; u++) d[m][s][u] = 0.0f;

    auto issue_w = [&](int c) {
        const int kg = kbase + c * 16;
        const int buf = c % 3;
#pragma unroll
        for (int r = 0; r < 4; r++) {
            int s = t + r * 128, k = s >> 5, seg = s & 31;
            cp_async16(smem_u32(&Wfs[buf][k][seg * 4]),
                       &W[(size_t)(kg + k) * NCOLS + n0 + seg * 4]);
        }
        CP_COMMIT();
    };
    float xreg[4];
    auto load_x = [&](int c) {
        const int kg = kbase + c * 16;
#pragma unroll
        for (int r = 0; r < 4; r++) {
            int i = t + r * 128, b = i >> 4, k = i & 15;
            xreg[r] = Xp[(size_t)b * XSTRIDE + kg + k];
        }
    };
    auto store_x = [&](int c) {
        uint32_t* dst = &Xs[c & 1][0][0];
#pragma unroll
        for (int r = 0; r < 4; r++) {
            int i = t + r * 128, b = i >> 4, k = i & 15;
            dst[b * 20 + k] = f2tf(xreg[r]);
        }
    };

    issue_w(0);
    if (NCH > 1) issue_w(1);
    load_x(0);
    store_x(0);
    if (NCH > 1) load_x(1);

    for (int c = 0; c < NCH; c++) {
        if (c + 1 < NCH) { CP_WAIT(1); } else { CP_WAIT(0); }
        __syncthreads();
        if (c + 2 < NCH) issue_w(c + 2);
        if (c + 1 < NCH) store_x(c + 1);
        if (c + 2 < NCH) load_x(c + 2);

        const int buf = c % 3;
        const uint32_t* Xc = &Xs[c & 1][0][0];
#pragma unroll
        for (int s = 0; s < 2; s++) {
            const int kA = s * 8;
            uint32_t a0[4], a1[4];
            a0[0] = Xc[g * 20 + kA + q];
            a0[1] = Xc[(g + 8) * 20 + kA + q];
            a0[2] = Xc[g * 20 + kA + q + 4];
            a0[3] = Xc[(g + 8) * 20 + kA + q + 4];
            a1[0] = Xc[(16 + g) * 20 + kA + q];
            a1[1] = Xc[(24 + g) * 20 + kA + q];
            a1[2] = Xc[(16 + g) * 20 + kA + q + 4];
            a1[3] = Xc[(24 + g) * 20 + kA + q + 4];
#pragma unroll
            for (int nt = 0; nt < 4; nt++) {
                const int col = warp * 32 + nt * 8 + g;
                uint32_t b0 = f2tf(Wfs[buf][s * 8 + q][col]);
                uint32_t b1 = f2tf(Wfs[buf][s * 8 + q + 4][col]);
                mma_tf32(d[0][nt], a0, b0, b1);
                mma_tf32(d[1][nt], a1, b0, b1);
            }
        }
    }
#pragma unroll
    for (int mt = 0; mt < 2; mt++) {
#pragma unroll
        for (int s = 0; s < 4; s++) {
            int col = n0 + warp * 32 + s * 8 + q * 2;
            if (EPI == 0) {
                size_t r0 = (size_t)(ksIdx * Bm + mt * 16 + g) * NCOLS + col;
                size_t r1 = (size_t)(ksIdx * Bm + mt * 16 + g + 8) * NCOLS + col;
                *reinterpret_cast<float2*>(&part[r0]) =
                    make_float2(d[mt][s][0], d[mt][s][1]);
                *reinterpret_cast<float2*>(&part[r1]) =
                    make_float2(d[mt][s][2], d[mt][s][3]);
            } else {
                size_t r0 = (size_t)(mt * 16 + g) * NCOLS + col;
                size_t r1 = (size_t)(mt * 16 + g + 8) * NCOLS + col;
                atomicAdd(&part[r0],     d[mt][s][0]);
                atomicAdd(&part[r0 + 1], d[mt][s][1]);
                atomicAdd(&part[r1],     d[mt][s][2]);
                atomicAdd(&part[r1 + 1], d[mt][s][3]);
            }
        }
    }
}

// Fused input GEMMs: blockIdx.z selects ssm / mlp. grid(40, KS_IN, 2).
__global__ __launch_bounds__(128)
void gemm_in_kernel(const float* __restrict__ X,
                    const float* __restrict__ W0,
                    const float* __restrict__ W1) {
    const float* W = (blockIdx.z == 0) ? W0 : W1;
    float* part    = (blockIdx.z == 0) ? g_p_ssm : g_p_mlp;
    constexpr int KPER = Dm / KS_IN;  // 320
    gemm32_tf2<KPER, Em, Dm, 0>(X, W, part, blockIdx.x * 128,
                                blockIdx.y * KPER, blockIdx.y);
}
// Output GEMM: atomicAdd directly into d_out (zeroed by ssm_kernel).
__global__ __launch_bounds__(128)
void gemm_out_kernel(const float* __restrict__ W, float* __restrict__ out) {
    constexpr int KPER = Em / KS_OUT;  // 160
    gemm32_tf2<KPER, Dm, Em, 1>(g_z, W, out, blockIdx.x * 128,
                                blockIdx.y * KPER, blockIdx.y);
}

// ---------------------------------------------------------------------------
// dbc GEMM: xt(32,5120) @ Wx(5120,192), f32x2 pipelined. grid(3, KS_DBC).
// ---------------------------------------------------------------------------
__global__ __launch_bounds__(128)
void dbc_gemm_kernel(const float* __restrict__ Wx) {
    __shared__ ull Wsb[2][32][32];
    __shared__ ull Xsb[2][32][33];

    const int t  = threadIdx.x;
    const int n0 = blockIdx.x * 64;
    constexpr int KPER = Em / KS_DBC;  // 128
    constexpr int NCH  = KPER / 32;    // 4
    const int kbase = blockIdx.y * KPER;
    const int cg = t & 15;
    const int rg = t >> 4;
    const int b0 = rg * 4;
    const int qu = cg * 2;

    ull acc[4][2];
#pragma unroll
    for (int j = 0; j < 4; j++) { acc[j][0] = 0ULL; acc[j][1] = 0ULL; }

    float xreg[8];
    {
        const int kg = kbase;
#pragma unroll
        for (int r = 0; r < 4; r++) {
            int s = t + r * 128, row = s >> 4, c16 = s & 15;
            cp_async16(smem_u32(&Wsb[0][row][c16 * 2]),
                       &Wx[(size_t)(kg + row) * 192 + n0 + c16 * 4]);
        }
        CP_COMMIT();
#pragma unroll
        for (int r = 0; r < 8; r++) {
            int i = t + r * 128, b = i >> 5, kk = i & 31;
            xreg[r] = g_xt[b * Em + kg + kk];
        }
    }

    for (int c = 0; c < NCH; c++) {
        const int p = c & 1;
#pragma unroll
        for (int r = 0; r < 8; r++) {
            int i = t + r * 128, b = i >> 5, kk = i & 31;
            Xsb[p][kk][b] = pack2(xreg[r], xreg[r]);
        }
        if (c + 1 < NCH) {
            const int kg = kbase + (c + 1) * 32;
#pragma unroll
            for (int r = 0; r < 4; r++) {
                int s = t + r * 128, row = s >> 4, c16 = s & 15;
                cp_async16(smem_u32(&Wsb[1 - p][row][c16 * 2]),
                           &Wx[(size_t)(kg + row) * 192 + n0 + c16 * 4]);
            }
            CP_COMMIT();
#pragma unroll
            for (int r = 0; r < 8; r++) {
                int i = t + r * 128, b = i >> 5, kk = i & 31;
                xreg[r] = g_xt[b * Em + kg + kk];
            }
            CP_WAIT(1);
        } else {
            CP_WAIT(0);
        }
        __syncthreads();
#pragma unroll
        for (int kk = 0; kk < 32; kk++) {
            ulonglong2 w = *reinterpret_cast<const ulonglong2*>(&Wsb[p][kk][qu]);
            ull xs[4] = {Xsb[p][kk][b0], Xsb[p][kk][b0 + 1],
                         Xsb[p][kk][b0 + 2], Xsb[p][kk][b0 + 3]};
#pragma unroll
            for (int j = 0; j < 4; j++) {
                fma2(acc[j][0], xs[j], w.x);
                fma2(acc[j][1], xs[j], w.y);
            }
        }
        __syncthreads();
    }
#pragma unroll
    for (int j = 0; j < 4; j++) {
        float2 a0 = unpack2(acc[j][0]);
        float2 a1 = unpack2(acc[j][1]);
        *reinterpret_cast<float4*>(
            &g_dbcp[((size_t)blockIdx.y * Bm + b0 + j) * 192 + n0 + cg * 4]) =
            make_float4(a0.x, a0.y, a1.x, a1.y);
    }
}

// ---------------------------------------------------------------------------
// conv + SiLU + precompute g_A = -exp(A_log).
// ---------------------------------------------------------------------------
__global__ __launch_bounds__(256)
void conv_silu_kernel(const float* __restrict__ conv_w,
                      const float* __restrict__ conv_b,
                      const float* __restrict__ conv_states,
                      const float* __restrict__ A_log) {
    int idx = blockIdx.x * 256 + threadIdx.x;
    float xssm = 0.0f, xmlp = 0.0f;
#pragma unroll
    for (int ks = 0; ks < KS_IN; ks++) {
        xssm += g_p_ssm[idx + ks * BE];
        xmlp += g_p_mlp[idx + ks * BE];
    }
    float c = conv_b[idx];
    c += conv_states[idx]          * conv_w[idx];
    c += conv_states[idx + BE]     * conv_w[idx + BE];
    c += conv_states[idx + 2 * BE] * conv_w[idx + 2 * BE];
    c += xssm                      * conv_w[idx + 3 * BE];
    g_xt[idx]  = silu_f(c);
    g_res[idx] = silu_f(xmlp);
    if (idx < Em * STn)
        g_A[idx] = -__expf(A_log[idx]);
}

// ---------------------------------------------------------------------------
// ssm: block-local dbc reduce (2 rows -> smem) + dt GEMM + SSM + z = y*res.
// h loads and s_dbc reads fully float4-vectorized (L1-wavefront reduction).
// Also zeroes d_out for gemm_out's atomic accumulation (exactly BD threads).
// ---------------------------------------------------------------------------
__global__ __launch_bounds__(256)
void ssm_kernel(const float* __restrict__ W_dt,
                const float* __restrict__ dt_bias,
                const float* __restrict__ Dv,
                const float* __restrict__ h,
                float* __restrict__ out) {
    __shared__ __align__(16) float s_dbc[384];
    const int t   = threadIdx.x;
    const int gid = blockIdx.x * 256 + t;   // [0, 16*Em)
    const int e   = gid % Em;
    const int b0  = (gid / Em) * 2;

    out[gid] = 0.0f;   // zero d_out slice for gemm_out atomics

    // reduce this block's two dbc rows from partials (L2-hot) into smem
    for (int idx = t; idx < 384; idx += 256) {
        int row = idx / 192;
        int col = idx - row * 192;
        int o = (b0 + row) * 192 + col;
        float s = 0.0f;
#pragma unroll
        for (int ks = 0; ks < KS_DBC; ks++) s += g_dbcp[ks * (Bm * 192) + o];
        s_dbc[idx] = s;
    }
    __syncthreads();

    // dt GEMM: float4 LDS on s_dbc, coalesced scalar LDG on W_dt
    float dt0 = 0.0f, dt1 = 0.0f;
#pragma unroll 2
    for (int k = 0; k < RK; k += 4) {
        float4 d0 = *reinterpret_cast<const float4*>(&s_dbc[k]);
        float4 d1 = *reinterpret_cast<const float4*>(&s_dbc[192 + k]);
        float w0 = W_dt[(size_t)(k    ) * Em + e];
        float w1 = W_dt[(size_t)(k + 1) * Em + e];
        float w2 = W_dt[(size_t)(k + 2) * Em + e];
        float w3 = W_dt[(size_t)(k + 3) * Em + e];
        dt0 += d0.x * w0 + d0.y * w1 + d0.z * w2 + d0.w * w3;
        dt1 += d1.x * w0 + d1.y * w1 + d1.z * w2 + d1.w * w3;
    }

    float bias = dt_bias[e];
    float dval = Dv[e];
    float An[STn];
#pragma unroll
    for (int n = 0; n < STn; n += 4) {
        float4 a = *reinterpret_cast<const float4*>(&g_A[(size_t)e * STn + n]);
        An[n] = a.x; An[n + 1] = a.y; An[n + 2] = a.z; An[n + 3] = a.w;
    }

    float dts[2] = {dt0, dt1};
#pragma unroll
    for (int j = 0; j < 2; j++) {
        int b = b0 + j;
        float s = dts[j] + bias;
        float dt = (s > 20.0f) ? s : __logf(1.0f + __expf(s));
        float xt = g_xt[b * Em + e];
        const float4* hb4 =
            reinterpret_cast<const float4*>(&h[((size_t)b * Em + e) * STn]);
        float y = 0.0f;
#pragma unroll
        for (int n4 = 0; n4 < 4; n4++) {
            float4 hv = hb4[n4];
            float4 Bv = *reinterpret_cast<const float4*>(&s_dbc[j * 192 + 160 + n4 * 4]);
            float4 Cv = *reinterpret_cast<const float4*>(&s_dbc[j * 192 + 176 + n4 * 4]);
            float hx[4] = {hv.x, hv.y, hv.z, hv.w};
            float Bx[4] = {Bv.x, Bv.y, Bv.z, Bv.w};
            float Cx[4] = {Cv.x, Cv.y, Cv.z, Cv.w};
#pragma unroll
            for (int u = 0; u < 4; u++) {
                float dA = __expf(dt * An[n4 * 4 + u]);
                float hn = hx[u] * dA + dt * Bx[u] * xt;
                y += hn * Cx[u];
            }
        }
        y += dval * xt;
        g_z[b * Em + e] = y * g_res[b * Em + e];
    }
}

// ---------------------------------------------------------------------------
extern "C" void kernel_launch(void* const* d_in, const int* in_sizes, int n_in,
                              void* d_out, int out_size) {
    const float* x        = (const float*)d_in[0];
    const float* W_in_ssm = (const float*)d_in[1];
    const float* W_in_mlp = (const float*)d_in[2];
    const float* W_out    = (const float*)d_in[3];
    const float* conv_w   = (const float*)d_in[4];
    const float* conv_b   = (const float*)d_in[5];
    const float* conv_st  = (const float*)d_in[6];
    const float* Wx       = (const float*)d_in[7];
    const float* W_dt     = (const float*)d_in[8];
    const float* dt_bias  = (const float*)d_in[9];
    const float* A_log    = (const float*)d_in[10];
    const float* Dvec     = (const float*)d_in[11];
    const float* h        = (const float*)d_in[12];
    float* out = (float*)d_out;

    gemm_in_kernel<<<dim3(40, KS_IN, 2), 128>>>(x, W_in_ssm, W_in_mlp);
    conv_silu_kernel<<<BE / 256, 256>>>(conv_w, conv_b, conv_st, A_log);
    dbc_gemm_kernel<<<dim3(3, KS_DBC), 128>>>(Wx);
    ssm_kernel<<<320, 256>>>(W_dt, dt_bias, Dvec, h, out);
    gemm_out_kernel<<<dim3(20, KS_OUT), 128>>>(W_out, out);
}

// round 16
// speedup vs baseline: 1.1182x; 1.0196x over previous
#include <cuda_runtime.h>
#include <cuda_bf16.h>
#include <cstdint>

#define Bm   32
#define Dm   2560
#define Em   5120
#define RK   160
#define STn  16
#define BE   (Bm*Em)
#define BD   (Bm*Dm)
#define KS_IN   8
#define KS_OUT  32
#define KS_DBC  40

typedef unsigned long long ull;

// -------- scratch ----------
__device__ float g_p_ssm[KS_IN * BE];
__device__ float g_p_mlp[KS_IN * BE];
__device__ float g_xt   [BE];
__device__ float g_res  [BE];
__device__ float g_dbcp [KS_DBC * Bm * 192];
__device__ float g_z    [BE];
__device__ float g_A    [Em * STn];   // -exp(A_log), precomputed once

// -------- helpers ----------
__device__ __forceinline__ ull pack2(float x, float y) {
    ull r;
    asm("mov.b64 %0, {%1,%2};" : "=l"(r) : "f"(x), "f"(y));
    return r;
}
__device__ __forceinline__ void fma2(ull& d, ull a, ull b) {
    asm("fma.rn.f32x2 %0, %1, %2, %0;" : "+l"(d) : "l"(a), "l"(b));
}
__device__ __forceinline__ float2 unpack2(ull v) {
    float2 r;
    asm("mov.b64 {%0,%1}, %2;" : "=f"(r.x), "=f"(r.y) : "l"(v));
    return r;
}
__device__ __forceinline__ float silu_f(float v) {
    return v * (1.0f / (1.0f + __expf(-v)));
}
__device__ __forceinline__ uint32_t smem_u32(const void* p) {
    uint32_t a;
    asm("{ .reg .u64 t; cvta.to.shared.u64 t, %1; cvt.u32.u64 %0, t; }"
        : "=r"(a) : "l"(p));
    return a;
}
__device__ __forceinline__ void cp_async16(uint32_t dst, const void* src) {
    asm volatile("cp.async.cg.shared.global [%0], [%1], 16;"
                 :: "r"(dst), "l"(src));
}
#define CP_COMMIT()  asm volatile("cp.async.commit_group;")
#define CP_WAIT(n)   asm volatile("cp.async.wait_group %0;" :: "n"(n))

__device__ __forceinline__ uint32_t f2tf(float v) {
    uint32_t u;
    asm("cvt.rna.tf32.f32 %0, %1;" : "=r"(u) : "f"(v));
    return u;
}
__device__ __forceinline__ void mma_tf32(float* d, const uint32_t* a,
                                         uint32_t b0, uint32_t b1) {
    asm volatile(
        "mma.sync.aligned.m16n8k8.row.col.f32.tf32.tf32.f32 "
        "{%0,%1,%2,%3}, {%4,%5,%6,%7}, {%8,%9}, {%0,%1,%2,%3};"
        : "+f"(d[0]), "+f"(d[1]), "+f"(d[2]), "+f"(d[3])
        : "r"(a[0]), "r"(a[1]), "r"(a[2]), "r"(a[3]), "r"(b0), "r"(b1));
}

// ---------------------------------------------------------------------------
// tf32 tensor-core 32-row GEMM: N-tile 128, 128 threads (4 warps).
// W: 3-stage cp.async pipeline, ONE __syncthreads per chunk.
// X: per-chunk tf32 double buffer, LDG prefetched one chunk ahead.
// EPI = 0: write partials to part[ksIdx]. EPI = 1: atomicAdd into part.
// ---------------------------------------------------------------------------
template <int KPER, int NCOLS, int XSTRIDE, int EPI>
__device__ __forceinline__
void gemm32_tf2(const float* __restrict__ Xp, const float* __restrict__ W,
                float* __restrict__ part, int n0, int kbase, int ksIdx) {
    __shared__ __align__(16) float    Wfs[3][16][136];
    __shared__ __align__(16) uint32_t Xs[2][32][20];

    const int t    = threadIdx.x;
    const int lane = t & 31;
    const int warp = t >> 5;
    const int g = lane >> 2;
    const int q = lane & 3;
    constexpr int NCH = KPER / 16;

    float d[2][4][4];
#pragma unroll
    for (int m = 0; m < 2; m++)
#pragma unroll
        for (int s = 0; s < 4; s++)
#pragma unroll
            for (int u = 0; u < 4; u++) d[m][s][u] = 0.0f;

    auto issue_w = [&](int c) {
        const int kg = kbase + c * 16;
        const int buf = c % 3;
#pragma unroll
        for (int r = 0; r < 4; r++) {
            int s = t + r * 128, k = s >> 5, seg = s & 31;
            cp_async16(smem_u32(&Wfs[buf][k][seg * 4]),
                       &W[(size_t)(kg + k) * NCOLS + n0 + seg * 4]);
        }
        CP_COMMIT();
    };
    float xreg[4];
    auto load_x = [&](int c) {
        const int kg = kbase + c * 16;
#pragma unroll
        for (int r = 0; r < 4; r++) {
            int i = t + r * 128, b = i >> 4, k = i & 15;
            xreg[r] = Xp[(size_t)b * XSTRIDE + kg + k];
        }
    };
    auto store_x = [&](int c) {
        uint32_t* dst = &Xs[c & 1][0][0];
#pragma unroll
        for (int r = 0; r < 4; r++) {
            int i = t + r * 128, b = i >> 4, k = i & 15;
            dst[b * 20 + k] = f2tf(xreg[r]);
        }
    };

    issue_w(0);
    if (NCH > 1) issue_w(1);
    load_x(0);
    store_x(0);
    if (NCH > 1) load_x(1);

    for (int c = 0; c < NCH; c++) {
        if (c + 1 < NCH) { CP_WAIT(1); } else { CP_WAIT(0); }
        __syncthreads();
        if (c + 2 < NCH) issue_w(c + 2);
        if (c + 1 < NCH) store_x(c + 1);
        if (c + 2 < NCH) load_x(c + 2);

        const int buf = c % 3;
        const uint32_t* Xc = &Xs[c & 1][0][0];
#pragma unroll
        for (int s = 0; s < 2; s++) {
            const int kA = s * 8;
            uint32_t a0[4], a1[4];
            a0[0] = Xc[g * 20 + kA + q];
            a0[1] = Xc[(g + 8) * 20 + kA + q];
            a0[2] = Xc[g * 20 + kA + q + 4];
            a0[3] = Xc[(g + 8) * 20 + kA + q + 4];
            a1[0] = Xc[(16 + g) * 20 + kA + q];
            a1[1] = Xc[(24 + g) * 20 + kA + q];
            a1[2] = Xc[(16 + g) * 20 + kA + q + 4];
            a1[3] = Xc[(24 + g) * 20 + kA + q + 4];
#pragma unroll
            for (int nt = 0; nt < 4; nt++) {
                const int col = warp * 32 + nt * 8 + g;
                uint32_t b0 = f2tf(Wfs[buf][s * 8 + q][col]);
                uint32_t b1 = f2tf(Wfs[buf][s * 8 + q + 4][col]);
                mma_tf32(d[0][nt], a0, b0, b1);
                mma_tf32(d[1][nt], a1, b0, b1);
            }
        }
    }
#pragma unroll
    for (int mt = 0; mt < 2; mt++) {
#pragma unroll
        for (int s = 0; s < 4; s++) {
            int col = n0 + warp * 32 + s * 8 + q * 2;
            if (EPI == 0) {
                size_t r0 = (size_t)(ksIdx * Bm + mt * 16 + g) * NCOLS + col;
                size_t r1 = (size_t)(ksIdx * Bm + mt * 16 + g + 8) * NCOLS + col;
                *reinterpret_cast<float2*>(&part[r0]) =
                    make_float2(d[mt][s][0], d[mt][s][1]);
                *reinterpret_cast<float2*>(&part[r1]) =
                    make_float2(d[mt][s][2], d[mt][s][3]);
            } else {
                size_t r0 = (size_t)(mt * 16 + g) * NCOLS + col;
                size_t r1 = (size_t)(mt * 16 + g + 8) * NCOLS + col;
                atomicAdd(&part[r0],     d[mt][s][0]);
                atomicAdd(&part[r0 + 1], d[mt][s][1]);
                atomicAdd(&part[r1],     d[mt][s][2]);
                atomicAdd(&part[r1 + 1], d[mt][s][3]);
            }
        }
    }
}

// Fused input GEMMs: blockIdx.z selects ssm / mlp. grid(40, KS_IN, 2).
__global__ __launch_bounds__(128)
void gemm_in_kernel(const float* __restrict__ X,
                    const float* __restrict__ W0,
                    const float* __restrict__ W1) {
    const float* W = (blockIdx.z == 0) ? W0 : W1;
    float* part    = (blockIdx.z == 0) ? g_p_ssm : g_p_mlp;
    constexpr int KPER = Dm / KS_IN;  // 320
    gemm32_tf2<KPER, Em, Dm, 0>(X, W, part, blockIdx.x * 128,
                                blockIdx.y * KPER, blockIdx.y);
}
// Output GEMM: atomicAdd directly into d_out (zeroed by ssm_kernel).
__global__ __launch_bounds__(128)
void gemm_out_kernel(const float* __restrict__ W, float* __restrict__ out) {
    constexpr int KPER = Em / KS_OUT;  // 160
    gemm32_tf2<KPER, Dm, Em, 1>(g_z, W, out, blockIdx.x * 128,
                                blockIdx.y * KPER, blockIdx.y);
}

// ---------------------------------------------------------------------------
// dbc GEMM: xt(32,5120) @ Wx(5120,192), f32x2 pipelined. grid(3, KS_DBC).
// ---------------------------------------------------------------------------
__global__ __launch_bounds__(128)
void dbc_gemm_kernel(const float* __restrict__ Wx) {
    __shared__ ull Wsb[2][32][32];
    __shared__ ull Xsb[2][32][33];

    const int t  = threadIdx.x;
    const int n0 = blockIdx.x * 64;
    constexpr int KPER = Em / KS_DBC;  // 128
    constexpr int NCH  = KPER / 32;    // 4
    const int kbase = blockIdx.y * KPER;
    const int cg = t & 15;
    const int rg = t >> 4;
    const int b0 = rg * 4;
    const int qu = cg * 2;

    ull acc[4][2];
#pragma unroll
    for (int j = 0; j < 4; j++) { acc[j][0] = 0ULL; acc[j][1] = 0ULL; }

    float xreg[8];
    {
        const int kg = kbase;
#pragma unroll
        for (int r = 0; r < 4; r++) {
            int s = t + r * 128, row = s >> 4, c16 = s & 15;
            cp_async16(smem_u32(&Wsb[0][row][c16 * 2]),
                       &Wx[(size_t)(kg + row) * 192 + n0 + c16 * 4]);
        }
        CP_COMMIT();
#pragma unroll
        for (int r = 0; r < 8; r++) {
            int i = t + r * 128, b = i >> 5, kk = i & 31;
            xreg[r] = g_xt[b * Em + kg + kk];
        }
    }

    for (int c = 0; c < NCH; c++) {
        const int p = c & 1;
#pragma unroll
        for (int r = 0; r < 8; r++) {
            int i = t + r * 128, b = i >> 5, kk = i & 31;
            Xsb[p][kk][b] = pack2(xreg[r], xreg[r]);
        }
        if (c + 1 < NCH) {
            const int kg = kbase + (c + 1) * 32;
#pragma unroll
            for (int r = 0; r < 4; r++) {
                int s = t + r * 128, row = s >> 4, c16 = s & 15;
                cp_async16(smem_u32(&Wsb[1 - p][row][c16 * 2]),
                           &Wx[(size_t)(kg + row) * 192 + n0 + c16 * 4]);
            }
            CP_COMMIT();
#pragma unroll
            for (int r = 0; r < 8; r++) {
                int i = t + r * 128, b = i >> 5, kk = i & 31;
                xreg[r] = g_xt[b * Em + kg + kk];
            }
            CP_WAIT(1);
        } else {
            CP_WAIT(0);
        }
        __syncthreads();
#pragma unroll
        for (int kk = 0; kk < 32; kk++) {
            ulonglong2 w = *reinterpret_cast<const ulonglong2*>(&Wsb[p][kk][qu]);
            ull xs[4] = {Xsb[p][kk][b0], Xsb[p][kk][b0 + 1],
                         Xsb[p][kk][b0 + 2], Xsb[p][kk][b0 + 3]};
#pragma unroll
            for (int j = 0; j < 4; j++) {
                fma2(acc[j][0], xs[j], w.x);
                fma2(acc[j][1], xs[j], w.y);
            }
        }
        __syncthreads();
    }
#pragma unroll
    for (int j = 0; j < 4; j++) {
        float2 a0 = unpack2(acc[j][0]);
        float2 a1 = unpack2(acc[j][1]);
        *reinterpret_cast<float4*>(
            &g_dbcp[((size_t)blockIdx.y * Bm + b0 + j) * 192 + n0 + cg * 4]) =
            make_float4(a0.x, a0.y, a1.x, a1.y);
    }
}

// ---------------------------------------------------------------------------
// conv + SiLU + precompute g_A = -exp(A_log).
// ---------------------------------------------------------------------------
__global__ __launch_bounds__(256)
void conv_silu_kernel(const float* __restrict__ conv_w,
                      const float* __restrict__ conv_b,
                      const float* __restrict__ conv_states,
                      const float* __restrict__ A_log) {
    int idx = blockIdx.x * 256 + threadIdx.x;
    float xssm = 0.0f, xmlp = 0.0f;
#pragma unroll
    for (int ks = 0; ks < KS_IN; ks++) {
        xssm += g_p_ssm[idx + ks * BE];
        xmlp += g_p_mlp[idx + ks * BE];
    }
    float c = conv_b[idx];
    c += conv_states[idx]          * conv_w[idx];
    c += conv_states[idx + BE]     * conv_w[idx + BE];
    c += conv_states[idx + 2 * BE] * conv_w[idx + 2 * BE];
    c += xssm                      * conv_w[idx + 3 * BE];
    g_xt[idx]  = silu_f(c);
    g_res[idx] = silu_f(xmlp);
    if (idx < Em * STn)
        g_A[idx] = -__expf(A_log[idx]);
}

// ---------------------------------------------------------------------------
// ssm: ONE b-row per thread (640 blocks x 256 -> 51% occ).
// Block-local dbc reduce (1 row -> smem) + dt GEMM + SSM + z = y*res.
// Zeroes d_out for gemm_out's atomic accumulation (first BD threads).
// ---------------------------------------------------------------------------
__global__ __launch_bounds__(256)
void ssm_kernel(const float* __restrict__ W_dt,
                const float* __restrict__ dt_bias,
                const float* __restrict__ Dv,
                const float* __restrict__ h,
                float* __restrict__ out) {
    __shared__ __align__(16) float s_dbc[192];
    const int t   = threadIdx.x;
    const int gid = blockIdx.x * 256 + t;   // [0, 32*Em)
    const int e   = gid % Em;
    const int b   = gid / Em;

    if (gid < BD) out[gid] = 0.0f;   // zero d_out for gemm_out atomics

    // reduce this block's dbc row from partials (L2-hot) into smem
    if (t < 192) {
        int o = b * 192 + t;
        float s = 0.0f;
#pragma unroll
        for (int ks = 0; ks < KS_DBC; ks++) s += g_dbcp[ks * (Bm * 192) + o];
        s_dbc[t] = s;
    }
    __syncthreads();

    // dt GEMM: float4 LDS on s_dbc, coalesced scalar LDG on W_dt
    float dtacc = 0.0f;
#pragma unroll 2
    for (int k = 0; k < RK; k += 4) {
        float4 d0 = *reinterpret_cast<const float4*>(&s_dbc[k]);
        float w0 = W_dt[(size_t)(k    ) * Em + e];
        float w1 = W_dt[(size_t)(k + 1) * Em + e];
        float w2 = W_dt[(size_t)(k + 2) * Em + e];
        float w3 = W_dt[(size_t)(k + 3) * Em + e];
        dtacc += d0.x * w0 + d0.y * w1 + d0.z * w2 + d0.w * w3;
    }

    float An[STn];
#pragma unroll
    for (int n = 0; n < STn; n += 4) {
        float4 a = *reinterpret_cast<const float4*>(&g_A[(size_t)e * STn + n]);
        An[n] = a.x; An[n + 1] = a.y; An[n + 2] = a.z; An[n + 3] = a.w;
    }

    float s = dtacc + dt_bias[e];
    float dt = (s > 20.0f) ? s : __logf(1.0f + __expf(s));
    float xt = g_xt[b * Em + e];
    const float4* hb4 =
        reinterpret_cast<const float4*>(&h[((size_t)b * Em + e) * STn]);
    float y = 0.0f;
#pragma unroll
    for (int n4 = 0; n4 < 4; n4++) {
        float4 hv = hb4[n4];
        float4 Bv = *reinterpret_cast<const float4*>(&s_dbc[160 + n4 * 4]);
        float4 Cv = *reinterpret_cast<const float4*>(&s_dbc[176 + n4 * 4]);
        float hx[4] = {hv.x, hv.y, hv.z, hv.w};
        float Bx[4] = {Bv.x, Bv.y, Bv.z, Bv.w};
        float Cx[4] = {Cv.x, Cv.y, Cv.z, Cv.w};
#pragma unroll
        for (int u = 0; u < 4; u++) {
            float dA = __expf(dt * An[n4 * 4 + u]);
            float hn = hx[u] * dA + dt * Bx[u] * xt;
            y += hn * Cx[u];
        }
    }
    y += Dv[e] * xt;
    g_z[b * Em + e] = y * g_res[b * Em + e];
}

// ---------------------------------------------------------------------------
extern "C" void kernel_launch(void* const* d_in, const int* in_sizes, int n_in,
                              void* d_out, int out_size) {
    const float* x        = (const float*)d_in[0];
    const float* W_in_ssm = (const float*)d_in[1];
    const float* W_in_mlp = (const float*)d_in[2];
    const float* W_out    = (const float*)d_in[3];
    const float* conv_w   = (const float*)d_in[4];
    const float* conv_b   = (const float*)d_in[5];
    const float* conv_st  = (const float*)d_in[6];
    const float* Wx       = (const float*)d_in[7];
    const float* W_dt     = (const float*)d_in[8];
    const float* dt_bias  = (const float*)d_in[9];
    const float* A_log    = (const float*)d_in[10];
    const float* Dvec     = (const float*)d_in[11];
    const float* h        = (const float*)d_in[12];
    float* out = (float*)d_out;

    gemm_in_kernel<<<dim3(40, KS_IN, 2), 128>>>(x, W_in_ssm, W_in_mlp);
    conv_silu_kernel<<<BE / 256, 256>>>(conv_w, conv_b, conv_st, A_log);
    dbc_gemm_kernel<<<dim3(3, KS_DBC), 128>>>(Wx);
    ssm_kernel<<<640, 256>>>(W_dt, dt_bias, Dvec, h, out);
    gemm_out_kernel<<<dim3(20, KS_OUT), 128>>>(W_out, out);
}

// round 17
// speedup vs baseline: 1.1518x; 1.0301x over previous
#include <cuda_runtime.h>
#include <cuda_bf16.h>
#include <cstdint>

#define Bm   32
#define Dm   2560
#define Em   5120
#define RK   160
#define STn  16
#define BE   (Bm*Em)
#define BD   (Bm*Dm)
#define KS_IN   8
#define KS_OUT  32
#define KS_DBC  40

typedef unsigned long long ull;

// -------- scratch ----------
__device__ float g_p_ssm[KS_IN * BE];
__device__ float g_p_mlp[KS_IN * BE];
__device__ float g_xt   [BE];
__device__ float g_res  [BE];
__device__ float g_dbc  [Bm * 192];   // reduced dbc (atomic accumulation)
__device__ float g_dtr  [BE];         // raw dt = dbc[:, :160] @ W_dt
__device__ float g_z    [BE];
__device__ float g_A    [Em * STn];   // -exp(A_log), precomputed once

// -------- helpers ----------
__device__ __forceinline__ ull pack2(float x, float y) {
    ull r;
    asm("mov.b64 %0, {%1,%2};" : "=l"(r) : "f"(x), "f"(y));
    return r;
}
__device__ __forceinline__ void fma2(ull& d, ull a, ull b) {
    asm("fma.rn.f32x2 %0, %1, %2, %0;" : "+l"(d) : "l"(a), "l"(b));
}
__device__ __forceinline__ float2 unpack2(ull v) {
    float2 r;
    asm("mov.b64 {%0,%1}, %2;" : "=f"(r.x), "=f"(r.y) : "l"(v));
    return r;
}
__device__ __forceinline__ float silu_f(float v) {
    return v * (1.0f / (1.0f + __expf(-v)));
}
__device__ __forceinline__ uint32_t smem_u32(const void* p) {
    uint32_t a;
    asm("{ .reg .u64 t; cvta.to.shared.u64 t, %1; cvt.u32.u64 %0, t; }"
        : "=r"(a) : "l"(p));
    return a;
}
__device__ __forceinline__ void cp_async16(uint32_t dst, const void* src) {
    asm volatile("cp.async.cg.shared.global [%0], [%1], 16;"
                 :: "r"(dst), "l"(src));
}
#define CP_COMMIT()  asm volatile("cp.async.commit_group;")
#define CP_WAIT(n)   asm volatile("cp.async.wait_group %0;" :: "n"(n))

__device__ __forceinline__ uint32_t f2tf(float v) {
    uint32_t u;
    asm("cvt.rna.tf32.f32 %0, %1;" : "=r"(u) : "f"(v));
    return u;
}
__device__ __forceinline__ void mma_tf32(float* d, const uint32_t* a,
                                         uint32_t b0, uint32_t b1) {
    asm volatile(
        "mma.sync.aligned.m16n8k8.row.col.f32.tf32.tf32.f32 "
        "{%0,%1,%2,%3}, {%4,%5,%6,%7}, {%8,%9}, {%0,%1,%2,%3};"
        : "+f"(d[0]), "+f"(d[1]), "+f"(d[2]), "+f"(d[3])
        : "r"(a[0]), "r"(a[1]), "r"(a[2]), "r"(a[3]), "r"(b0), "r"(b1));
}

// ---------------------------------------------------------------------------
// tf32 tensor-core 32-row GEMM: N-tile 128, 128 threads (4 warps).
// W: 3-stage cp.async pipeline, ONE __syncthreads per chunk.
// X: per-chunk tf32 double buffer, LDG prefetched one chunk ahead.
// EPI = 0: write partials to part[ksIdx]. EPI = 1: atomicAdd into part.
// ---------------------------------------------------------------------------
template <int KPER, int NCOLS, int XSTRIDE, int EPI>
__device__ __forceinline__
void gemm32_tf2(const float* __restrict__ Xp, const float* __restrict__ W,
                float* __restrict__ part, int n0, int kbase, int ksIdx) {
    __shared__ __align__(16) float    Wfs[3][16][136];
    __shared__ __align__(16) uint32_t Xs[2][32][20];

    const int t    = threadIdx.x;
    const int lane = t & 31;
    const int warp = t >> 5;
    const int g = lane >> 2;
    const int q = lane & 3;
    constexpr int NCH = KPER / 16;

    float d[2][4][4];
#pragma unroll
    for (int m = 0; m < 2; m++)
#pragma unroll
        for (int s = 0; s < 4; s++)
#pragma unroll
            for (int u = 0; u < 4; u++) d[m][s][u] = 0.0f;

    auto issue_w = [&](int c) {
        const int kg = kbase + c * 16;
        const int buf = c % 3;
#pragma unroll
        for (int r = 0; r < 4; r++) {
            int s = t + r * 128, k = s >> 5, seg = s & 31;
            cp_async16(smem_u32(&Wfs[buf][k][seg * 4]),
                       &W[(size_t)(kg + k) * NCOLS + n0 + seg * 4]);
        }
        CP_COMMIT();
    };
    float xreg[4];
    auto load_x = [&](int c) {
        const int kg = kbase + c * 16;
#pragma unroll
        for (int r = 0; r < 4; r++) {
            int i = t + r * 128, b = i >> 4, k = i & 15;
            xreg[r] = Xp[(size_t)b * XSTRIDE + kg + k];
        }
    };
    auto store_x = [&](int c) {
        uint32_t* dst = &Xs[c & 1][0][0];
#pragma unroll
        for (int r = 0; r < 4; r++) {
            int i = t + r * 128, b = i >> 4, k = i & 15;
            dst[b * 20 + k] = f2tf(xreg[r]);
        }
    };

    issue_w(0);
    if (NCH > 1) issue_w(1);
    load_x(0);
    store_x(0);
    if (NCH > 1) load_x(1);

    for (int c = 0; c < NCH; c++) {
        if (c + 1 < NCH) { CP_WAIT(1); } else { CP_WAIT(0); }
        __syncthreads();
        if (c + 2 < NCH) issue_w(c + 2);
        if (c + 1 < NCH) store_x(c + 1);
        if (c + 2 < NCH) load_x(c + 2);

        const int buf = c % 3;
        const uint32_t* Xc = &Xs[c & 1][0][0];
#pragma unroll
        for (int s = 0; s < 2; s++) {
            const int kA = s * 8;
            uint32_t a0[4], a1[4];
            a0[0] = Xc[g * 20 + kA + q];
            a0[1] = Xc[(g + 8) * 20 + kA + q];
            a0[2] = Xc[g * 20 + kA + q + 4];
            a0[3] = Xc[(g + 8) * 20 + kA + q + 4];
            a1[0] = Xc[(16 + g) * 20 + kA + q];
            a1[1] = Xc[(24 + g) * 20 + kA + q];
            a1[2] = Xc[(16 + g) * 20 + kA + q + 4];
            a1[3] = Xc[(24 + g) * 20 + kA + q + 4];
#pragma unroll
            for (int nt = 0; nt < 4; nt++) {
                const int col = warp * 32 + nt * 8 + g;
                uint32_t b0 = f2tf(Wfs[buf][s * 8 + q][col]);
                uint32_t b1 = f2tf(Wfs[buf][s * 8 + q + 4][col]);
                mma_tf32(d[0][nt], a0, b0, b1);
                mma_tf32(d[1][nt], a1, b0, b1);
            }
        }
    }
#pragma unroll
    for (int mt = 0; mt < 2; mt++) {
#pragma unroll
        for (int s = 0; s < 4; s++) {
            int col = n0 + warp * 32 + s * 8 + q * 2;
            if (EPI == 0) {
                size_t r0 = (size_t)(ksIdx * Bm + mt * 16 + g) * NCOLS + col;
                size_t r1 = (size_t)(ksIdx * Bm + mt * 16 + g + 8) * NCOLS + col;
                *reinterpret_cast<float2*>(&part[r0]) =
                    make_float2(d[mt][s][0], d[mt][s][1]);
                *reinterpret_cast<float2*>(&part[r1]) =
                    make_float2(d[mt][s][2], d[mt][s][3]);
            } else {
                size_t r0 = (size_t)(mt * 16 + g) * NCOLS + col;
                size_t r1 = (size_t)(mt * 16 + g + 8) * NCOLS + col;
                atomicAdd(&part[r0],     d[mt][s][0]);
                atomicAdd(&part[r0 + 1], d[mt][s][1]);
                atomicAdd(&part[r1],     d[mt][s][2]);
                atomicAdd(&part[r1 + 1], d[mt][s][3]);
            }
        }
    }
}

// Fused input GEMMs: blockIdx.z selects ssm / mlp. grid(40, KS_IN, 2).
__global__ __launch_bounds__(128)
void gemm_in_kernel(const float* __restrict__ X,
                    const float* __restrict__ W0,
                    const float* __restrict__ W1) {
    const float* W = (blockIdx.z == 0) ? W0 : W1;
    float* part    = (blockIdx.z == 0) ? g_p_ssm : g_p_mlp;
    constexpr int KPER = Dm / KS_IN;  // 320
    gemm32_tf2<KPER, Em, Dm, 0>(X, W, part, blockIdx.x * 128,
                                blockIdx.y * KPER, blockIdx.y);
}
// Output GEMM: atomicAdd directly into d_out (zeroed by ssm_kernel).
__global__ __launch_bounds__(128)
void gemm_out_kernel(const float* __restrict__ W, float* __restrict__ out) {
    constexpr int KPER = Em / KS_OUT;  // 160
    gemm32_tf2<KPER, Dm, Em, 1>(g_z, W, out, blockIdx.x * 128,
                                blockIdx.y * KPER, blockIdx.y);
}
// dt projection: g_dtr = g_dbc[:, :160] @ W_dt (32 x 5120 x 160). grid(40).
__global__ __launch_bounds__(128)
void dt_gemm_kernel(const float* __restrict__ W_dt) {
    gemm32_tf2<RK, Em, 192, 0>(g_dbc, W_dt, g_dtr, blockIdx.x * 128, 0, 0);
}

// ---------------------------------------------------------------------------
// dbc GEMM: xt(32,5120) @ Wx(5120,192), f32x2 pipelined, atomic epilogue
// into g_dbc (zeroed by conv_silu). grid(3, KS_DBC).
// ---------------------------------------------------------------------------
__global__ __launch_bounds__(128)
void dbc_gemm_kernel(const float* __restrict__ Wx) {
    __shared__ ull Wsb[2][32][32];
    __shared__ ull Xsb[2][32][33];

    const int t  = threadIdx.x;
    const int n0 = blockIdx.x * 64;
    constexpr int KPER = Em / KS_DBC;  // 128
    constexpr int NCH  = KPER / 32;    // 4
    const int kbase = blockIdx.y * KPER;
    const int cg = t & 15;
    const int rg = t >> 4;
    const int b0 = rg * 4;
    const int qu = cg * 2;

    ull acc[4][2];
#pragma unroll
    for (int j = 0; j < 4; j++) { acc[j][0] = 0ULL; acc[j][1] = 0ULL; }

    float xreg[8];
    {
        const int kg = kbase;
#pragma unroll
        for (int r = 0; r < 4; r++) {
            int s = t + r * 128, row = s >> 4, c16 = s & 15;
            cp_async16(smem_u32(&Wsb[0][row][c16 * 2]),
                       &Wx[(size_t)(kg + row) * 192 + n0 + c16 * 4]);
        }
        CP_COMMIT();
#pragma unroll
        for (int r = 0; r < 8; r++) {
            int i = t + r * 128, b = i >> 5, kk = i & 31;
            xreg[r] = g_xt[b * Em + kg + kk];
        }
    }

    for (int c = 0; c < NCH; c++) {
        const int p = c & 1;
#pragma unroll
        for (int r = 0; r < 8; r++) {
            int i = t + r * 128, b = i >> 5, kk = i & 31;
            Xsb[p][kk][b] = pack2(xreg[r], xreg[r]);
        }
        if (c + 1 < NCH) {
            const int kg = kbase + (c + 1) * 32;
#pragma unroll
            for (int r = 0; r < 4; r++) {
                int s = t + r * 128, row = s >> 4, c16 = s & 15;
                cp_async16(smem_u32(&Wsb[1 - p][row][c16 * 2]),
                           &Wx[(size_t)(kg + row) * 192 + n0 + c16 * 4]);
            }
            CP_COMMIT();
#pragma unroll
            for (int r = 0; r < 8; r++) {
                int i = t + r * 128, b = i >> 5, kk = i & 31;
                xreg[r] = g_xt[b * Em + kg + kk];
            }
            CP_WAIT(1);
        } else {
            CP_WAIT(0);
        }
        __syncthreads();
#pragma unroll
        for (int kk = 0; kk < 32; kk++) {
            ulonglong2 w = *reinterpret_cast<const ulonglong2*>(&Wsb[p][kk][qu]);
            ull xs[4] = {Xsb[p][kk][b0], Xsb[p][kk][b0 + 1],
                         Xsb[p][kk][b0 + 2], Xsb[p][kk][b0 + 3]};
#pragma unroll
            for (int j = 0; j < 4; j++) {
                fma2(acc[j][0], xs[j], w.x);
                fma2(acc[j][1], xs[j], w.y);
            }
        }
        __syncthreads();
    }
#pragma unroll
    for (int j = 0; j < 4; j++) {
        float2 a0 = unpack2(acc[j][0]);
        float2 a1 = unpack2(acc[j][1]);
        float* dst = &g_dbc[(b0 + j) * 192 + n0 + cg * 4];
        atomicAdd(dst,     a0.x);
        atomicAdd(dst + 1, a0.y);
        atomicAdd(dst + 2, a1.x);
        atomicAdd(dst + 3, a1.y);
    }
}

// ---------------------------------------------------------------------------
// conv + SiLU + precompute g_A = -exp(A_log) + zero g_dbc.
// ---------------------------------------------------------------------------
__global__ __launch_bounds__(256)
void conv_silu_kernel(const float* __restrict__ conv_w,
                      const float* __restrict__ conv_b,
                      const float* __restrict__ conv_states,
                      const float* __restrict__ A_log) {
    int idx = blockIdx.x * 256 + threadIdx.x;
    float xssm = 0.0f, xmlp = 0.0f;
#pragma unroll
    for (int ks = 0; ks < KS_IN; ks++) {
        xssm += g_p_ssm[idx + ks * BE];
        xmlp += g_p_mlp[idx + ks * BE];
    }
    float c = conv_b[idx];
    c += conv_states[idx]          * conv_w[idx];
    c += conv_states[idx + BE]     * conv_w[idx + BE];
    c += conv_states[idx + 2 * BE] * conv_w[idx + 2 * BE];
    c += xssm                      * conv_w[idx + 3 * BE];
    g_xt[idx]  = silu_f(c);
    g_res[idx] = silu_f(xmlp);
    if (idx < Em * STn)
        g_A[idx] = -__expf(A_log[idx]);
    if (idx < Bm * 192)
        g_dbc[idx] = 0.0f;
}

// ---------------------------------------------------------------------------
// ssm: pure elementwise SSM. Reads precomputed g_dtr; B/C broadcast from
// L2-hot g_dbc; h/An via float4. Zeroes d_out for gemm_out atomics.
// grid 640 x 256, one (b,e) per thread; b uniform per block.
// ---------------------------------------------------------------------------
__global__ __launch_bounds__(256)
void ssm_kernel(const float* __restrict__ dt_bias,
                const float* __restrict__ Dv,
                const float* __restrict__ h,
                float* __restrict__ out) {
    const int gid = blockIdx.x * 256 + threadIdx.x;  // [0, 32*Em)
    const int e   = gid % Em;
    const int b   = gid / Em;

    if (gid < BD) out[gid] = 0.0f;

    float An[STn];
#pragma unroll
    for (int n = 0; n < STn; n += 4) {
        float4 a = *reinterpret_cast<const float4*>(&g_A[(size_t)e * STn + n]);
        An[n] = a.x; An[n + 1] = a.y; An[n + 2] = a.z; An[n + 3] = a.w;
    }

    float s = g_dtr[gid] + dt_bias[e];
    float dt = (s > 20.0f) ? s : __logf(1.0f + __expf(s));
    float xt = g_xt[gid];
    const float4* hb4 =
        reinterpret_cast<const float4*>(&h[(size_t)gid * STn]);
    float y = 0.0f;
#pragma unroll
    for (int n4 = 0; n4 < 4; n4++) {
        float4 hv = hb4[n4];
        float4 Bv = *reinterpret_cast<const float4*>(&g_dbc[b * 192 + 160 + n4 * 4]);
        float4 Cv = *reinterpret_cast<const float4*>(&g_dbc[b * 192 + 176 + n4 * 4]);
        float hx[4] = {hv.x, hv.y, hv.z, hv.w};
        float Bx[4] = {Bv.x, Bv.y, Bv.z, Bv.w};
        float Cx[4] = {Cv.x, Cv.y, Cv.z, Cv.w};
#pragma unroll
        for (int u = 0; u < 4; u++) {
            float dA = __expf(dt * An[n4 * 4 + u]);
            float hn = hx[u] * dA + dt * Bx[u] * xt;
            y += hn * Cx[u];
        }
    }
    y += Dv[e] * xt;
    g_z[gid] = y * g_res[gid];
}

// ---------------------------------------------------------------------------
extern "C" void kernel_launch(void* const* d_in, const int* in_sizes, int n_in,
                              void* d_out, int out_size) {
    const float* x        = (const float*)d_in[0];
    const float* W_in_ssm = (const float*)d_in[1];
    const float* W_in_mlp = (const float*)d_in[2];
    const float* W_out    = (const float*)d_in[3];
    const float* conv_w   = (const float*)d_in[4];
    const float* conv_b   = (const float*)d_in[5];
    const float* conv_st  = (const float*)d_in[6];
    const float* Wx       = (const float*)d_in[7];
    const float* W_dt     = (const float*)d_in[8];
    const float* dt_bias  = (const float*)d_in[9];
    const float* A_log    = (const float*)d_in[10];
    const float* Dvec     = (const float*)d_in[11];
    const float* h        = (const float*)d_in[12];
    float* out = (float*)d_out;

    gemm_in_kernel<<<dim3(40, KS_IN, 2), 128>>>(x, W_in_ssm, W_in_mlp);
    conv_silu_kernel<<<BE / 256, 256>>>(conv_w, conv_b, conv_st, A_log);
    dbc_gemm_kernel<<<dim3(3, KS_DBC), 128>>>(Wx);
    dt_gemm_kernel<<<40, 128>>>(W_dt);
    ssm_kernel<<<640, 256>>>(dt_bias, Dvec, h, out);
    gemm_out_kernel<<<dim3(20, KS_OUT), 128>>>(W_out, out);
}